// round 3
// baseline (speedup 1.0000x reference)
#include <cuda_runtime.h>

#define IMG_H 512
#define IMG_W 512
#define N_PLANES 256          // B*C = 8*32
#define BAND_ROWS 132
#define N_BANDS 4             // 4*132 = 528 >= 512
#define N_ITERS (BAND_ROWS + 8)   // 140, multiple of 10
#define TPB 128               // 128 threads * 4 cols = 512 cols

__device__ double g_acc;

__global__ void sc_init() {
    if (threadIdx.x == 0) g_acc = 0.0;
}

__global__ void sc_final(float* out) {
    if (threadIdx.x == 0) out[0] = (float)(g_acc * 0.125);  // mean over batch of 8
}

// Load one padded row. Each thread issues ONE aligned 16B load for its own
// columns; left/right neighbor float4s come from warp shuffles. Lanes 0/31
// patch the warp-boundary halo with a predicated 16B load (32B/warp-row extra
// L2 traffic instead of 3x amplification).
__device__ __forceinline__ void load_row(
    const float* __restrict__ base, int L, int tid, int lane,
    float4& vL, float4& vC, float4& vR)
{
    const int Lc = min(max(L, 0), IMG_H - 1);
    const float m = (L >= 0 && L < IMG_H) ? 1.0f : 0.0f;
    const float4* rp = (const float4*)(base + (size_t)Lc * IMG_W) + tid;

    float4 b = __ldg(rp);
    vC = make_float4(b.x * m, b.y * m, b.z * m, b.w * m);

    vL.x = __shfl_up_sync(0xffffffffu, vC.x, 1);
    vL.y = __shfl_up_sync(0xffffffffu, vC.y, 1);
    vL.z = __shfl_up_sync(0xffffffffu, vC.z, 1);
    vL.w = __shfl_up_sync(0xffffffffu, vC.w, 1);
    vR.x = __shfl_down_sync(0xffffffffu, vC.x, 1);
    vR.y = __shfl_down_sync(0xffffffffu, vC.y, 1);
    vR.z = __shfl_down_sync(0xffffffffu, vC.z, 1);
    vR.w = __shfl_down_sync(0xffffffffu, vC.w, 1);

    if (lane == 0) {
        if (tid > 0) {
            float4 a = __ldg(rp - 1);
            vL = make_float4(a.x * m, a.y * m, a.z * m, a.w * m);
        } else {
            vL = make_float4(0.f, 0.f, 0.f, 0.f);
        }
    }
    if (lane == 31) {
        if (tid < TPB - 1) {
            float4 c = __ldg(rp + 1);
            vR = make_float4(c.x * m, c.y * m, c.z * m, c.w * m);
        } else {
            vR = make_float4(0.f, 0.f, 0.f, 0.f);
        }
    }
}

__global__ void __launch_bounds__(TPB, 7) sc_main(const float* __restrict__ img) {
    const int tid   = threadIdx.x;
    const int lane  = tid & 31;
    const int plane = blockIdx.x;
    const int band  = blockIdx.y;
    const int rowStart = band * BAND_ROWS;
    const int c0 = tid << 2;
    const float* base = img + (size_t)plane * (IMG_H * IMG_W);

    // cnt_w per owned column (window-overlap count along W)
    const float cw0 = (float)(min(c0 + 0, 4) + min(IMG_W - 1 - (c0 + 0), 4) + 1);
    const float cw1 = (float)(min(c0 + 1, 4) + min(IMG_W - 1 - (c0 + 1), 4) + 1);
    const float cw2 = (float)(min(c0 + 2, 4) + min(IMG_W - 1 - (c0 + 2), 4) + 1);
    const float cw3 = (float)(min(c0 + 3, 4) + min(IMG_W - 1 - (c0 + 3), 4) + 1);

    // horizontal-9-sum ring lives in SMEM (private slot per thread, no barriers)
    __shared__ float4 hs[10][TPB];
#pragma unroll
    for (int i = 0; i < 10; i++) hs[i][tid] = make_float4(0.f, 0.f, 0.f, 0.f);

    float4 xring[5];    // raw x, rows L-4..L (registers)
#pragma unroll
    for (int i = 0; i < 5; i++)  xring[i] = make_float4(0.f, 0.f, 0.f, 0.f);
    float4 S = make_float4(0.f, 0.f, 0.f, 0.f);   // vertical 9-sum of hsum
    float acc = 0.f;

    // software pipeline: prefetch row i=0 (load + shuffle both in prefetch stage)
    float4 cvL, cvC, cvR;
    load_row(base, rowStart - 4, tid, lane, cvL, cvC, cvR);

    for (int it = 0; it < N_ITERS / 10; ++it) {
#pragma unroll
        for (int k = 0; k < 10; ++k) {
            const int i = it * 10 + k;

            // prefetch row i+1 BEFORE consuming row i (hides LDG + SHFL latency)
            float4 nvL, nvC, nvR;
            load_row(base, rowStart - 4 + i + 1, tid, lane, nvL, nvC, nvR);

            // horizontal 9-sums for the 4 owned columns (sliding)
            float s8 = cvL.x + cvL.y + cvL.z + cvL.w
                     + cvC.x + cvC.y + cvC.z + cvC.w + cvR.x;
            float4 hn;
            hn.x = s8;
            hn.y = hn.x - cvL.x + cvR.y;
            hn.z = hn.y - cvL.y + cvR.z;
            hn.w = hn.z - cvL.z + cvR.w;

            // slide vertical sum: S covers hsum rows [L-8, L] after update
            const float4 hold = hs[(k + 1) % 10][tid];   // hsum row L-9
            S.x += hn.x - hold.x;
            S.y += hn.y - hold.y;
            S.z += hn.z - hold.z;
            S.w += hn.w - hold.w;
            hs[k][tid] = hn;

            const float4 xe = xring[(k + 1) % 5];        // x at row r = L-4
            xring[k % 5] = cvC;

            // advance pipeline
            cvL = nvL; cvC = nvC; cvR = nvR;

            // emit row r = L - 4 = rowStart - 8 + i
            const int r = rowStart - 8 + i;
            if (i >= 8 && r < IMG_H) {
                const float cnth = (float)(min(r, 4) + min(IMG_H - 1 - r, 4) + 1);
                float coef, t;
                coef = fmaf(cnth, cw0, 81.0f);
                t = fmaf(coef, xe.x, -2.0f * S.x); acc = fmaf(xe.x, t, acc);
                coef = fmaf(cnth, cw1, 81.0f);
                t = fmaf(coef, xe.y, -2.0f * S.y); acc = fmaf(xe.y, t, acc);
                coef = fmaf(cnth, cw2, 81.0f);
                t = fmaf(coef, xe.z, -2.0f * S.z); acc = fmaf(xe.z, t, acc);
                coef = fmaf(cnth, cw3, 81.0f);
                t = fmaf(coef, xe.w, -2.0f * S.w); acc = fmaf(xe.w, t, acc);
            }
        }
    }

    // block reduction: warp shuffle -> smem -> one double atomic per CTA
    __shared__ float warpsum[TPB / 32];
    float v = acc;
#pragma unroll
    for (int off = 16; off; off >>= 1) v += __shfl_down_sync(0xffffffffu, v, off);
    if ((tid & 31) == 0) warpsum[tid >> 5] = v;
    __syncthreads();
    if (tid == 0) {
        float s = warpsum[0] + warpsum[1] + warpsum[2] + warpsum[3];
        atomicAdd(&g_acc, (double)s);
    }
}

extern "C" void kernel_launch(void* const* d_in, const int* in_sizes, int n_in,
                              void* d_out, int out_size) {
    const float* img = (const float*)d_in[0];
    sc_init<<<1, 32>>>();
    dim3 grid(N_PLANES, N_BANDS);
    sc_main<<<grid, TPB>>>(img);
    sc_final<<<1, 32>>>((float*)d_out);
}

// round 4
// speedup vs baseline: 1.6004x; 1.6004x over previous
#include <cuda_runtime.h>

#define IMG_H 512
#define IMG_W 512
#define N_PLANES 256          // B*C = 8*32
#define BAND_ROWS 132
#define N_BANDS 4             // 4*132 = 528 >= 512
#define N_ITERS (BAND_ROWS + 8)   // 140, multiple of 10
#define TPB 128               // 128 threads * 4 cols = 512 cols

__device__ double g_acc;

__global__ void sc_init() {
    if (threadIdx.x == 0) g_acc = 0.0;
}

__global__ void sc_final(float* out) {
    if (threadIdx.x == 0) out[0] = (float)(g_acc * 0.125);  // mean over batch of 8
}

// Load one padded row (only called when the row is in-image).
// Edge threads zero their missing neighbor via predicated select.
__device__ __forceinline__ void load_row(
    const float4* __restrict__ rp, bool t0, bool t127,
    float4& vL, float4& vC, float4& vR)
{
    vC = __ldg(rp);
    if (t0)   vL = make_float4(0.f, 0.f, 0.f, 0.f);
    else      vL = __ldg(rp - 1);
    if (t127) vR = make_float4(0.f, 0.f, 0.f, 0.f);
    else      vR = __ldg(rp + 1);
}

__global__ void __launch_bounds__(TPB, 7) sc_main(const float* __restrict__ img) {
    const int tid   = threadIdx.x;
    const int plane = blockIdx.x;
    const int band  = blockIdx.y;
    const int rowStart = band * BAND_ROWS;
    const int c0 = tid << 2;
    const float* base = img + (size_t)plane * (IMG_H * IMG_W);

    const bool t0   = (tid == 0);
    const bool t127 = (tid == TPB - 1);
    const bool thB  = t0 || t127;   // thread owns border columns

    // cnt_w per owned column (window-overlap count along W); 9 in interior
    const float cw0 = (float)(min(c0 + 0, 4) + min(IMG_W - 1 - (c0 + 0), 4) + 1);
    const float cw1 = (float)(min(c0 + 1, 4) + min(IMG_W - 1 - (c0 + 1), 4) + 1);
    const float cw2 = (float)(min(c0 + 2, 4) + min(IMG_W - 1 - (c0 + 2), 4) + 1);
    const float cw3 = (float)(min(c0 + 3, 4) + min(IMG_W - 1 - (c0 + 3), 4) + 1);

    // horizontal-9-sum ring in SMEM (private slot per thread, no barriers)
    __shared__ float4 hs[10][TPB];
#pragma unroll
    for (int i = 0; i < 10; i++) hs[i][tid] = make_float4(0.f, 0.f, 0.f, 0.f);

    float4 xring[5];    // raw x, rows L-4..L (registers)
#pragma unroll
    for (int i = 0; i < 5; i++)  xring[i] = make_float4(0.f, 0.f, 0.f, 0.f);
    float4 S = make_float4(0.f, 0.f, 0.f, 0.f);   // vertical 9-sum of hsum

    float acc_sq = 0.f;   // sum of x^2 over emitted pixels
    float acc_xs = 0.f;   // sum of x * S
    float acc_c  = 0.f;   // border correction: sum (81 - cnth*cw) * x^2

    // base pointer for the float4 column of this thread at row (rowStart-4)
    const float4* row0 = (const float4*)(base) + (size_t)(rowStart - 4) * (IMG_W / 4) + tid;

    // software pipeline: prefetch row i=0
    float4 cvL, cvC, cvR;
    {
        const int L = rowStart - 4;
        if ((unsigned)L < (unsigned)IMG_H) {
            load_row(row0, t0, t127, cvL, cvC, cvR);
        } else {
            cvL = cvC = cvR = make_float4(0.f, 0.f, 0.f, 0.f);
        }
    }

    for (int it = 0; it < N_ITERS / 10; ++it) {
        const float4* rit = row0 + (size_t)(it * 10 + 1) * (IMG_W / 4);
#pragma unroll
        for (int k = 0; k < 10; ++k) {
            const int i = it * 10 + k;

            // prefetch row i+1 (uniform validity branch) BEFORE consuming row i
            float4 nvL, nvC, nvR;
            {
                const int Ln = rowStart - 3 + i;
                if ((unsigned)Ln < (unsigned)IMG_H) {
                    load_row(rit + (size_t)k * (IMG_W / 4), t0, t127, nvL, nvC, nvR);
                } else {
                    nvL = nvC = nvR = make_float4(0.f, 0.f, 0.f, 0.f);
                }
            }

            // horizontal 9-sums for the 4 owned columns (sliding)
            float s8 = ((cvL.x + cvL.y) + (cvL.z + cvL.w))
                     + ((cvC.x + cvC.y) + (cvC.z + cvC.w)) + cvR.x;
            float4 hn;
            hn.x = s8;
            hn.y = hn.x - cvL.x + cvR.y;
            hn.z = hn.y - cvL.y + cvR.z;
            hn.w = hn.z - cvL.z + cvR.w;

            // slide vertical sum: S covers hsum rows [L-8, L] after update
            const float4 hold = hs[(k + 1) % 10][tid];   // hsum row L-9
            S.x += hn.x - hold.x;
            S.y += hn.y - hold.y;
            S.z += hn.z - hold.z;
            S.w += hn.w - hold.w;
            hs[k][tid] = hn;

            const float4 xe = xring[(k + 1) % 5];        // x at row r = L-4
            xring[k % 5] = cvC;

            // advance pipeline
            cvL = nvL; cvC = nvC; cvR = nvR;

            // emit row r = rowStart - 8 + i
            const int r = rowStart - 8 + i;
            if (i >= 8 && r < IMG_H) {
                acc_sq = fmaf(xe.x, xe.x, acc_sq);
                acc_sq = fmaf(xe.y, xe.y, acc_sq);
                acc_sq = fmaf(xe.z, xe.z, acc_sq);
                acc_sq = fmaf(xe.w, xe.w, acc_sq);
                acc_xs = fmaf(xe.x, S.x, acc_xs);
                acc_xs = fmaf(xe.y, S.y, acc_xs);
                acc_xs = fmaf(xe.z, S.z, acc_xs);
                acc_xs = fmaf(xe.w, S.w, acc_xs);

                // border correction: (81 - cnth*cw) != 0 only for border rows
                // (uniform branch, 8 rows/image) or border threads (tid 0/127)
                const bool rowB = (r < 4) | (r > IMG_H - 5);
                if (rowB | thB) {
                    const float cnth = (float)(min(r, 4) + min(IMG_H - 1 - r, 4) + 1);
                    float c;
                    c = 81.0f - cnth * cw0; acc_c = fmaf(c, xe.x * xe.x, acc_c);
                    c = 81.0f - cnth * cw1; acc_c = fmaf(c, xe.y * xe.y, acc_c);
                    c = 81.0f - cnth * cw2; acc_c = fmaf(c, xe.z * xe.z, acc_c);
                    c = 81.0f - cnth * cw3; acc_c = fmaf(c, xe.w * xe.w, acc_c);
                }
            }
        }
    }

    // per-thread combine: (81+cnth*cw)x^2 - 2xS  ==  162x^2 - corr - 2xS
    float acc = fmaf(162.0f, acc_sq, fmaf(-2.0f, acc_xs, -acc_c));

    // block reduction: warp shuffle -> smem -> one double atomic per CTA
    __shared__ float warpsum[TPB / 32];
    float v = acc;
#pragma unroll
    for (int off = 16; off; off >>= 1) v += __shfl_down_sync(0xffffffffu, v, off);
    if ((tid & 31) == 0) warpsum[tid >> 5] = v;
    __syncthreads();
    if (tid == 0) {
        float s = warpsum[0] + warpsum[1] + warpsum[2] + warpsum[3];
        atomicAdd(&g_acc, (double)s);
    }
}

extern "C" void kernel_launch(void* const* d_in, const int* in_sizes, int n_in,
                              void* d_out, int out_size) {
    const float* img = (const float*)d_in[0];
    sc_init<<<1, 32>>>();
    dim3 grid(N_PLANES, N_BANDS);
    sc_main<<<grid, TPB>>>(img);
    sc_final<<<1, 32>>>((float*)d_out);
}